// round 7
// baseline (speedup 1.0000x reference)
#include <cuda_runtime.h>
#include <cuda_bf16.h>
#include <math.h>

// Problem constants
#define BT   256
#define TT   250
#define II   700
#define HH   128
#define OO   20
#define B_J0 0.01f
#define BETA 1.8f

// Output layout: output[256*20], s1[256*128], s2[256*128], A_norm[1]
#define OUT_OFF_ACC  0
#define OUT_OFF_S1   (BT*OO)
#define OUT_OFF_S2   (OUT_OFF_S1 + BT*HH)
#define OUT_OFF_NORM (OUT_OFF_S2 + BT*HH)

// Static device scratch (no allocations allowed)
__device__ float g_xin[TT * BT * HH];   // 32 MB
__device__ float g_npart[64];

// ---------------------------------------------------------------------------
// f32x2 helpers (FFMA2 only reachable via PTX)
// ---------------------------------------------------------------------------
__device__ __forceinline__ unsigned long long ffma2(unsigned long long a,
                                                    unsigned long long b,
                                                    unsigned long long c)
{
    unsigned long long d;
    asm("fma.rn.f32x2 %0, %1, %2, %3;" : "=l"(d) : "l"(a), "l"(b), "l"(c));
    return d;
}
__device__ __forceinline__ unsigned long long pack2(float lo, float hi)
{
    unsigned long long d;
    asm("mov.b64 %0, {%1, %2};" : "=l"(d) : "f"(lo), "f"(hi));
    return d;
}
__device__ __forceinline__ float2 unpack2(unsigned long long v)
{
    float lo, hi;
    asm("mov.b64 {%0, %1}, %2;" : "=f"(lo), "=f"(hi) : "l"(v));
    return make_float2(lo, hi);
}

// ---------------------------------------------------------------------------
// Kernel 1: xin = einsum('bti,ih->tbh', x, w_ih1) + b_ih1
// 256x128 CTA tile, 16Mx8N per thread, FFMA2 over M-pairs.
// Per output element: single accumulator, strictly ascending k (each f32x2
// lane is an independent IEEE fp32 FMA) -> bit-identical to round-3 GEMM.
// ---------------------------------------------------------------------------
#define GTM 256
#define KT  8
#define NKTILE ((II + KT - 1) / KT)   // 88

__global__ __launch_bounds__(256, 1) void gemm_xin_kernel(
    const float* __restrict__ x,      // [B,T,I] row stride 700
    const float* __restrict__ w,      // [I,H]
    const float* __restrict__ bias,   // [H]
    float* __restrict__ xin)          // [T,B,H]
{
    __shared__ float As[2][KT][GTM];  // 16 KB
    __shared__ float Bs[2][KT][HH];   // 8 KB

    const int tid = threadIdx.x;
    const int tx = tid & 15;          // n subtile
    const int ty = tid >> 4;          // m subtile
    const int bm = blockIdx.x * GTM;
    const int n0 = tx * 8;
    const int m0 = ty * 16;

    unsigned long long acc[8][8];     // [m-pair][n]
#pragma unroll
    for (int p = 0; p < 8; p++)
#pragma unroll
        for (int j = 0; j < 8; j++) acc[p][j] = 0ull;

    // loader mapping: thread loads A row (bm + tid), B row (k0 + tid>>5)
    const float* xrow = x + (size_t)(bm + tid) * II;
    const int bk = tid >> 5;          // 0..7
    const int bn = (tid & 31) * 4;    // 0..124

    // prefetch tile 0
    {
        float4 a0 = *(const float4*)(xrow + 0);
        float4 a1 = *(const float4*)(xrow + 4);
        float4 bv = *(const float4*)(w + (size_t)bk * HH + bn);
        As[0][0][tid] = a0.x; As[0][1][tid] = a0.y;
        As[0][2][tid] = a0.z; As[0][3][tid] = a0.w;
        As[0][4][tid] = a1.x; As[0][5][tid] = a1.y;
        As[0][6][tid] = a1.z; As[0][7][tid] = a1.w;
        *(float4*)&Bs[0][bk][bn] = bv;
    }
    __syncthreads();

    for (int tI = 0; tI < NKTILE; tI++) {
        const int buf = tI & 1;
        float4 na0, na1, nbv;
        const bool has = (tI + 1 < NKTILE);
        if (has) {
            int k0 = (tI + 1) * KT;
            na0 = (k0 + 3 < II) ? *(const float4*)(xrow + k0)
                                : make_float4(0.f, 0.f, 0.f, 0.f);
            na1 = (k0 + 7 < II) ? *(const float4*)(xrow + k0 + 4)
                                : make_float4(0.f, 0.f, 0.f, 0.f);
            int kk = k0 + bk;
            nbv = (kk < II) ? *(const float4*)(w + (size_t)kk * HH + bn)
                            : make_float4(0.f, 0.f, 0.f, 0.f);
        }

#pragma unroll
        for (int k = 0; k < KT; k++) {
            unsigned long long a[8];
            const ulonglong2* Ap = (const ulonglong2*)&As[buf][k][m0];
            ulonglong2 av;
            av = Ap[0]; a[0] = av.x; a[1] = av.y;
            av = Ap[1]; a[2] = av.x; a[3] = av.y;
            av = Ap[2]; a[4] = av.x; a[5] = av.y;
            av = Ap[3]; a[6] = av.x; a[7] = av.y;
            float4 b0 = *(const float4*)&Bs[buf][k][n0];
            float4 b1 = *(const float4*)&Bs[buf][k][n0 + 4];
            float bj[8] = {b0.x, b0.y, b0.z, b0.w, b1.x, b1.y, b1.z, b1.w};
#pragma unroll
            for (int j = 0; j < 8; j++) {
                unsigned long long bb = pack2(bj[j], bj[j]);
#pragma unroll
                for (int p = 0; p < 8; p++)
                    acc[p][j] = ffma2(a[p], bb, acc[p][j]);
            }
        }

        if (has) {
            int nb = buf ^ 1;
            As[nb][0][tid] = na0.x; As[nb][1][tid] = na0.y;
            As[nb][2][tid] = na0.z; As[nb][3][tid] = na0.w;
            As[nb][4][tid] = na1.x; As[nb][5][tid] = na1.y;
            As[nb][6][tid] = na1.z; As[nb][7][tid] = na1.w;
            *(float4*)&Bs[nb][bk][bn] = nbv;
        }
        __syncthreads();
    }

    // epilogue: row m = b*250 + t -> xin[(t*256 + b)*128 + n], add bias
    float bn8[8];
#pragma unroll
    for (int j = 0; j < 8; j++) bn8[j] = bias[n0 + j];

#pragma unroll
    for (int p = 0; p < 8; p++) {
        float lo[8], hi[8];
#pragma unroll
        for (int j = 0; j < 8; j++) {
            float2 v = unpack2(acc[p][j]);
            lo[j] = v.x; hi[j] = v.y;
        }
        int mg = bm + m0 + 2 * p;
#pragma unroll
        for (int half = 0; half < 2; half++) {
            const float* vv = half ? hi : lo;
            int m = mg + half;
            int bb = m / TT;
            int tt = m - bb * TT;
            float* op = xin + ((size_t)tt * BT + bb) * HH + n0;
            float4 v0, v1;
            v0.x = __fadd_rn(vv[0], bn8[0]);
            v0.y = __fadd_rn(vv[1], bn8[1]);
            v0.z = __fadd_rn(vv[2], bn8[2]);
            v0.w = __fadd_rn(vv[3], bn8[3]);
            v1.x = __fadd_rn(vv[4], bn8[4]);
            v1.y = __fadd_rn(vv[5], bn8[5]);
            v1.z = __fadd_rn(vv[6], bn8[6]);
            v1.w = __fadd_rn(vv[7], bn8[7]);
            *(float4*)(op)     = v0;
            *(float4*)(op + 4) = v1;
        }
    }
}

// ---------------------------------------------------------------------------
// Segmented sparse dot: 4 per-warp segments in ascending order, single
// accumulator, pure __fadd_rn -> bit-identical to dense sequential k-loop.
// ---------------------------------------------------------------------------
__device__ __forceinline__ float seg_dot128(const float* __restrict__ wsm,
                                            const int* __restrict__ lst,
                                            const unsigned* __restrict__ cnt,
                                            int h)
{
    float q = 0.f;
#pragma unroll
    for (int s = 0; s < 4; s++) {
        int c = __popc(cnt[s]);
        const int* L = lst + (s << 5);
#pragma unroll 4
        for (int i = 0; i < c; i++) q = __fadd_rn(q, wsm[(L[i] << 7) + h]);
    }
    return q;
}

__device__ __forceinline__ float seg_dot20(const float* __restrict__ wsm,
                                           const int* __restrict__ lst,
                                           const unsigned* __restrict__ cnt,
                                           int o)
{
    float q = 0.f;
#pragma unroll
    for (int s = 0; s < 4; s++) {
        int c = __popc(cnt[s]);
        const int* L = lst + (s << 5);
#pragma unroll 4
        for (int i = 0; i < c; i++) q = __fadd_rn(q, wsm[L[i] * OO + o]);
    }
    return q;
}

// exp(-1/tau): correctly-rounded fp32 via double (feeds spike recurrence)
__device__ __forceinline__ float decay(float tau)
{
    float u = __fdiv_rn(-1.0f, tau);
    return (float)exp((double)u);
}

// ---------------------------------------------------------------------------
// Kernel 2: the scan. 128 CTAs x 256 threads; CTA c owns batch rows 2c, 2c+1.
// Parity-double-buffered spike lists -> 2 __syncthreads per timestep.
// All elementwise math: non-contracted __fmul_rn/__fadd_rn/__fsub_rn in
// the reference's exact association order.
// ---------------------------------------------------------------------------
#define SCAN_SMEM_BYTES ((16384*3 + 2560)*4 + 1024*4 + 32*4)

__global__ __launch_bounds__(256, 1) void scan_kernel(
    const float* __restrict__ xin,        // [T,B,H]
    const float* __restrict__ mask,       // [2,H,H]
    const float* __restrict__ w_h1h1, const float* __restrict__ b_h1h1,
    const float* __restrict__ w_h1h2, const float* __restrict__ b_h1h2,
    const float* __restrict__ w_h2h2, const float* __restrict__ b_h2h2,
    const float* __restrict__ w_h2o,  const float* __restrict__ b_h2o,
    const float* __restrict__ tau_adp_h1, const float* __restrict__ tau_adp_h2,
    const float* __restrict__ tau_m_h1,   const float* __restrict__ tau_m_h2,
    const float* __restrict__ tau_m_o,
    const float* __restrict__ hid1_mem0,  const float* __restrict__ hid2_mem0,
    const float* __restrict__ out_mem0,
    float* __restrict__ out)
{
    extern __shared__ unsigned char smraw[];
    float* w11s = (float*)smraw;            // 16384 (masked)
    float* w12s = w11s + 16384;             // 16384
    float* w22s = w12s + 16384;             // 16384 (masked)
    float* w2os = w22s + 16384;             // 2560
    int*   list1 = (int*)(w2os + 2560);     // [2][2][128]
    int*   list2 = list1 + 512;             // [2][2][128]
    unsigned* m1s = (unsigned*)(list2 + 512); // [2][8]
    unsigned* m2s = m1s + 16;                 // [2][8]

    const int tid  = threadIdx.x;
    const int r    = tid >> 7;
    const int h    = tid & 127;
    const int wid  = tid >> 5;
    const int lane = tid & 31;
    const int seg  = wid & 3;
    const int grow = blockIdx.x * 2 + r;

    for (int i = tid; i < 16384; i += 256) {
        w11s[i] = __fmul_rn(w_h1h1[i], mask[i]);
        w12s[i] = w_h1h2[i];
        w22s[i] = __fmul_rn(w_h2h2[i], mask[16384 + i]);
    }
    for (int i = tid; i < 2560; i += 256) w2os[i] = w_h2o[i];
    if (tid < 16) { m1s[tid] = 0u; m2s[tid] = 0u; }

    const float a1 = decay(tau_m_h1[h]);
    const float r1 = decay(tau_adp_h1[h]);
    const float a2 = decay(tau_m_h2[h]);
    const float r2 = decay(tau_adp_h2[h]);
    const float oma1 = __fsub_rn(1.0f, a1);
    const float omr1 = __fsub_rn(1.0f, r1);
    const float oma2 = __fsub_rn(1.0f, a2);
    const float omr2 = __fsub_rn(1.0f, r2);
    const float b11r = b_h1h1[h];
    const float b12a = b_h1h2[h];
    const float b12b = b_h2h2[h];

    float h1m = hid1_mem0[grow * HH + h];
    float h2m = hid2_mem0[grow * HH + h];
    float b1 = B_J0, b2 = B_J0;
    float h1sp = 0.f, h2sp = 0.f;
    float s1c = 0.f, s2c = 0.f;

    const bool ro = (wid == 0) || (wid == 5);
    float om = 0.f, aoo = 0.f, omao = 0.f, bo = 0.f, acc = 0.f;
    if (ro && lane < OO) {
        om   = out_mem0[grow * OO + lane];
        aoo  = decay(tau_m_o[lane]);
        omao = __fsub_rn(1.0f, aoo);
        bo   = b_h2o[lane];
    }
    __syncthreads();

    float xt = xin[((size_t)0 * BT + grow) * HH + h];
    int p = 0;

    for (int t = 0; t < TT; t++) {
        float xnext = (t + 1 < TT) ? __ldg(&xin[((size_t)(t + 1) * BT + grow) * HH + h]) : 0.f;
        const int q = p ^ 1;

        // ---- layer 1 ----
        float d11 = seg_dot128(w11s, list1 + p * 256 + (r << 7), m1s + p * 8 + r * 4, h);
        float i1 = __fadd_rn(__fadd_rn(xt, d11), b11r);
        b1 = __fadd_rn(__fmul_rn(r1, b1), __fmul_rn(omr1, h1sp));
        float B1 = __fadd_rn(B_J0, __fmul_rn(BETA, b1));
        h1m = __fsub_rn(__fadd_rn(__fmul_rn(h1m, a1), __fmul_rn(oma1, i1)),
                        __fmul_rn(B1, h1sp));
        float sp1 = (__fsub_rn(h1m, B1) > 0.0f) ? 1.0f : 0.0f;
        s1c += sp1;

        unsigned bal1 = __ballot_sync(0xffffffffu, sp1 != 0.0f);
        if (lane == 0) m1s[q * 8 + wid] = bal1;
        if (sp1 != 0.0f) {
            int pos = __popc(bal1 & ((1u << lane) - 1u));
            list1[q * 256 + (r << 7) + (seg << 5) + pos] = h;
        }
        __syncthreads();

        // ---- layer 2 ----
        float d12 = seg_dot128(w12s, list1 + q * 256 + (r << 7), m1s + q * 8 + r * 4, h);
        float d22 = seg_dot128(w22s, list2 + p * 256 + (r << 7), m2s + p * 8 + r * 4, h);
        float i2 = __fadd_rn(__fadd_rn(__fadd_rn(d12, b12a), d22), b12b);
        b2 = __fadd_rn(__fmul_rn(r2, b2), __fmul_rn(omr2, h2sp));
        float B2 = __fadd_rn(B_J0, __fmul_rn(BETA, b2));
        h2m = __fsub_rn(__fadd_rn(__fmul_rn(h2m, a2), __fmul_rn(oma2, i2)),
                        __fmul_rn(B2, h2sp));
        float sp2 = (__fsub_rn(h2m, B2) > 0.0f) ? 1.0f : 0.0f;
        s2c += sp2;

        unsigned bal2 = __ballot_sync(0xffffffffu, sp2 != 0.0f);
        if (lane == 0) m2s[q * 8 + wid] = bal2;
        if (sp2 != 0.0f) {
            int pos = __popc(bal2 & ((1u << lane) - 1u));
            list2[q * 256 + (r << 7) + (seg << 5) + pos] = h;
        }
        __syncthreads();

        // ---- readout (warps 0 and 5; uses NEW h2 spikes) ----
        if (ro) {
            int oo = (lane < OO) ? lane : 0;
            float d2o = seg_dot20(w2os, list2 + q * 256 + (r << 7), m2s + q * 8 + r * 4, oo);
            float io = __fadd_rn(d2o, bo);
            om = __fadd_rn(__fmul_rn(om, aoo), __fmul_rn(omao, io));
            float v = (lane < OO) ? om : -3.4e38f;
#pragma unroll
            for (int d = 16; d; d >>= 1) v = fmaxf(v, __shfl_xor_sync(0xffffffffu, v, d));
            float e = (lane < OO) ? expf(__fsub_rn(om, v)) : 0.f;
            float ssum = e;
#pragma unroll
            for (int d = 16; d; d >>= 1) ssum += __shfl_xor_sync(0xffffffffu, ssum, d);
            if (t > 10) acc = __fadd_rn(acc, __fdiv_rn(e, ssum));
        }

        h1sp = sp1;
        h2sp = sp2;
        xt = xnext;
        p = q;
    }

    out[OUT_OFF_S1 + grow * HH + h] = __fdiv_rn(s1c, (float)TT);
    out[OUT_OFF_S2 + grow * HH + h] = __fdiv_rn(s2c, (float)TT);
    if (ro && lane < OO) out[OUT_OFF_ACC + grow * OO + lane] = acc;
}

// ---------------------------------------------------------------------------
// Kernel 3a/3b: A_norm (deterministic two-pass)
// ---------------------------------------------------------------------------
__global__ __launch_bounds__(256) void norm_part_kernel(
    const float* __restrict__ w11, const float* __restrict__ w22,
    const float* __restrict__ mask)
{
    __shared__ float red[256];
    int i = blockIdx.x * 256 + threadIdx.x;   // 64 blocks x 256 = 16384
    float s = fabsf(__fmul_rn(w11[i], mask[i]))
            + fabsf(__fmul_rn(w22[i], mask[16384 + i]));
    red[threadIdx.x] = s;
    __syncthreads();
    for (int d = 128; d > 0; d >>= 1) {
        if (threadIdx.x < d) red[threadIdx.x] += red[threadIdx.x + d];
        __syncthreads();
    }
    if (threadIdx.x == 0) g_npart[blockIdx.x] = red[0];
}

__global__ void norm_finish_kernel(float* __restrict__ out)
{
    int lane = threadIdx.x;      // 64 threads = 2 warps
    __shared__ float w[2];
    float s = g_npart[lane];
#pragma unroll
    for (int d = 16; d; d >>= 1) s += __shfl_xor_sync(0xffffffffu, s, d);
    if ((lane & 31) == 0) w[lane >> 5] = s;
    __syncthreads();
    if (lane == 0) out[OUT_OFF_NORM] = w[0] + w[1];
}

// ---------------------------------------------------------------------------
extern "C" void kernel_launch(void* const* d_in, const int* in_sizes, int n_in,
                              void* d_out, int out_size)
{
    const float* x          = (const float*)d_in[0];
    const float* mask       = (const float*)d_in[1];
    const float* w_ih1      = (const float*)d_in[2];
    const float* b_ih1      = (const float*)d_in[3];
    const float* w_h1h1     = (const float*)d_in[4];
    const float* b_h1h1     = (const float*)d_in[5];
    const float* w_h1h2     = (const float*)d_in[6];
    const float* b_h1h2     = (const float*)d_in[7];
    const float* w_h2h2     = (const float*)d_in[8];
    const float* b_h2h2     = (const float*)d_in[9];
    const float* w_h2o      = (const float*)d_in[10];
    const float* b_h2o      = (const float*)d_in[11];
    const float* tau_adp_h1 = (const float*)d_in[12];
    const float* tau_adp_h2 = (const float*)d_in[13];
    const float* tau_m_h1   = (const float*)d_in[14];
    const float* tau_m_h2   = (const float*)d_in[15];
    const float* tau_m_o    = (const float*)d_in[16];
    const float* hid1_mem0  = (const float*)d_in[17];
    const float* hid2_mem0  = (const float*)d_in[18];
    const float* out_mem0   = (const float*)d_in[19];
    float* out = (float*)d_out;

    float* xin = nullptr;
    cudaGetSymbolAddress((void**)&xin, g_xin);

    cudaFuncSetAttribute(scan_kernel, cudaFuncAttributeMaxDynamicSharedMemorySize,
                         SCAN_SMEM_BYTES);

    gemm_xin_kernel<<<(BT * TT) / GTM, 256>>>(x, w_ih1, b_ih1, xin);
    scan_kernel<<<BT / 2, 256, SCAN_SMEM_BYTES>>>(
        xin, mask, w_h1h1, b_h1h1, w_h1h2, b_h1h2, w_h2h2, b_h2h2,
        w_h2o, b_h2o, tau_adp_h1, tau_adp_h2, tau_m_h1, tau_m_h2, tau_m_o,
        hid1_mem0, hid2_mem0, out_mem0, out);
    norm_part_kernel<<<64, 256>>>(w_h1h1, w_h2h2, mask);
    norm_finish_kernel<<<1, 64>>>(out);
}

// round 8
// speedup vs baseline: 1.4595x; 1.4595x over previous
#include <cuda_runtime.h>
#include <cuda_bf16.h>
#include <math.h>

// Problem constants
#define BT   256
#define TT   250
#define II   700
#define HH   128
#define OO   20
#define B_J0 0.01f
#define BETA 1.8f

// Output layout: output[256*20], s1[256*128], s2[256*128], A_norm[1]
#define OUT_OFF_ACC  0
#define OUT_OFF_S1   (BT*OO)
#define OUT_OFF_S2   (OUT_OFF_S1 + BT*HH)
#define OUT_OFF_NORM (OUT_OFF_S2 + BT*HH)

// Static device scratch (no allocations allowed)
__device__ float g_xin[TT * BT * HH];   // 32 MB
__device__ float g_om[TT * BT * OO];    // 5.12 MB
__device__ float g_npart[64];

// ---------------------------------------------------------------------------
// f32x2 helpers
// ---------------------------------------------------------------------------
__device__ __forceinline__ unsigned long long ffma2(unsigned long long a,
                                                    unsigned long long b,
                                                    unsigned long long c)
{
    unsigned long long d;
    asm("fma.rn.f32x2 %0, %1, %2, %3;" : "=l"(d) : "l"(a), "l"(b), "l"(c));
    return d;
}
__device__ __forceinline__ unsigned long long pack2(float lo, float hi)
{
    unsigned long long d;
    asm("mov.b64 %0, {%1, %2};" : "=l"(d) : "f"(lo), "f"(hi));
    return d;
}
__device__ __forceinline__ float2 unpack2(unsigned long long v)
{
    float lo, hi;
    asm("mov.b64 {%0, %1}, %2;" : "=f"(lo), "=f"(hi) : "l"(v));
    return make_float2(lo, hi);
}

// ---------------------------------------------------------------------------
// Kernel 1: xin = einsum('bti,ih->tbh', x, w_ih1) + b_ih1   (unchanged R7)
// ---------------------------------------------------------------------------
#define GTM 256
#define KT  8
#define NKTILE ((II + KT - 1) / KT)   // 88

__global__ __launch_bounds__(256, 1) void gemm_xin_kernel(
    const float* __restrict__ x,
    const float* __restrict__ w,
    const float* __restrict__ bias,
    float* __restrict__ xin)
{
    __shared__ float As[2][KT][GTM];
    __shared__ float Bs[2][KT][HH];

    const int tid = threadIdx.x;
    const int tx = tid & 15;
    const int ty = tid >> 4;
    const int bm = blockIdx.x * GTM;
    const int n0 = tx * 8;
    const int m0 = ty * 16;

    unsigned long long acc[8][8];
#pragma unroll
    for (int p = 0; p < 8; p++)
#pragma unroll
        for (int j = 0; j < 8; j++) acc[p][j] = 0ull;

    const float* xrow = x + (size_t)(bm + tid) * II;
    const int bk = tid >> 5;
    const int bn = (tid & 31) * 4;

    {
        float4 a0 = *(const float4*)(xrow + 0);
        float4 a1 = *(const float4*)(xrow + 4);
        float4 bv = *(const float4*)(w + (size_t)bk * HH + bn);
        As[0][0][tid] = a0.x; As[0][1][tid] = a0.y;
        As[0][2][tid] = a0.z; As[0][3][tid] = a0.w;
        As[0][4][tid] = a1.x; As[0][5][tid] = a1.y;
        As[0][6][tid] = a1.z; As[0][7][tid] = a1.w;
        *(float4*)&Bs[0][bk][bn] = bv;
    }
    __syncthreads();

    for (int tI = 0; tI < NKTILE; tI++) {
        const int buf = tI & 1;
        float4 na0, na1, nbv;
        const bool has = (tI + 1 < NKTILE);
        if (has) {
            int k0 = (tI + 1) * KT;
            na0 = (k0 + 3 < II) ? *(const float4*)(xrow + k0)
                                : make_float4(0.f, 0.f, 0.f, 0.f);
            na1 = (k0 + 7 < II) ? *(const float4*)(xrow + k0 + 4)
                                : make_float4(0.f, 0.f, 0.f, 0.f);
            int kk = k0 + bk;
            nbv = (kk < II) ? *(const float4*)(w + (size_t)kk * HH + bn)
                            : make_float4(0.f, 0.f, 0.f, 0.f);
        }

#pragma unroll
        for (int k = 0; k < KT; k++) {
            unsigned long long a[8];
            const ulonglong2* Ap = (const ulonglong2*)&As[buf][k][m0];
            ulonglong2 av;
            av = Ap[0]; a[0] = av.x; a[1] = av.y;
            av = Ap[1]; a[2] = av.x; a[3] = av.y;
            av = Ap[2]; a[4] = av.x; a[5] = av.y;
            av = Ap[3]; a[6] = av.x; a[7] = av.y;
            float4 b0 = *(const float4*)&Bs[buf][k][n0];
            float4 b1 = *(const float4*)&Bs[buf][k][n0 + 4];
            float bj[8] = {b0.x, b0.y, b0.z, b0.w, b1.x, b1.y, b1.z, b1.w};
#pragma unroll
            for (int j = 0; j < 8; j++) {
                unsigned long long bb = pack2(bj[j], bj[j]);
#pragma unroll
                for (int p = 0; p < 8; p++)
                    acc[p][j] = ffma2(a[p], bb, acc[p][j]);
            }
        }

        if (has) {
            int nb = buf ^ 1;
            As[nb][0][tid] = na0.x; As[nb][1][tid] = na0.y;
            As[nb][2][tid] = na0.z; As[nb][3][tid] = na0.w;
            As[nb][4][tid] = na1.x; As[nb][5][tid] = na1.y;
            As[nb][6][tid] = na1.z; As[nb][7][tid] = na1.w;
            *(float4*)&Bs[nb][bk][bn] = nbv;
        }
        __syncthreads();
    }

    float bn8[8];
#pragma unroll
    for (int j = 0; j < 8; j++) bn8[j] = bias[n0 + j];

#pragma unroll
    for (int p = 0; p < 8; p++) {
        float lo[8], hi[8];
#pragma unroll
        for (int j = 0; j < 8; j++) {
            float2 v = unpack2(acc[p][j]);
            lo[j] = v.x; hi[j] = v.y;
        }
        int mg = bm + m0 + 2 * p;
#pragma unroll
        for (int half = 0; half < 2; half++) {
            const float* vv = half ? hi : lo;
            int m = mg + half;
            int bb = m / TT;
            int tt = m - bb * TT;
            float* op = xin + ((size_t)tt * BT + bb) * HH + n0;
            float4 v0, v1;
            v0.x = __fadd_rn(vv[0], bn8[0]);
            v0.y = __fadd_rn(vv[1], bn8[1]);
            v0.z = __fadd_rn(vv[2], bn8[2]);
            v0.w = __fadd_rn(vv[3], bn8[3]);
            v1.x = __fadd_rn(vv[4], bn8[4]);
            v1.y = __fadd_rn(vv[5], bn8[5]);
            v1.z = __fadd_rn(vv[6], bn8[6]);
            v1.w = __fadd_rn(vv[7], bn8[7]);
            *(float4*)(op)     = v0;
            *(float4*)(op + 4) = v1;
        }
    }
}

// ---------------------------------------------------------------------------
// Pipelined gather-sum over a contiguous, 4-padded ascending index list.
// Padding indices point at row 128 (all zeros) -> q + 0.0f, bit-exact.
// Single accumulator, ascending order: bit-identical to dense sequential FMA.
// ---------------------------------------------------------------------------
__device__ __forceinline__ float gather128(const float* __restrict__ wsm,
                                           const int* __restrict__ lst,
                                           int cpad, int h)
{
    float q = 0.f;
    int nb = cpad >> 2;
    if (nb == 0) return q;
    const int4* L = (const int4*)lst;
    int4 id = L[0];
    float a0 = wsm[(id.x << 7) + h], a1 = wsm[(id.y << 7) + h],
          a2 = wsm[(id.z << 7) + h], a3 = wsm[(id.w << 7) + h];
    for (int b = 1; b < nb; b++) {
        int4 idn = L[b];
        float n0 = wsm[(idn.x << 7) + h], n1 = wsm[(idn.y << 7) + h],
              n2 = wsm[(idn.z << 7) + h], n3 = wsm[(idn.w << 7) + h];
        q = __fadd_rn(q, a0); q = __fadd_rn(q, a1);
        q = __fadd_rn(q, a2); q = __fadd_rn(q, a3);
        a0 = n0; a1 = n1; a2 = n2; a3 = n3;
    }
    q = __fadd_rn(q, a0); q = __fadd_rn(q, a1);
    q = __fadd_rn(q, a2); q = __fadd_rn(q, a3);
    return q;
}

__device__ __forceinline__ float gather20(const float* __restrict__ wsm,
                                          const int* __restrict__ lst,
                                          int cpad, int o)
{
    float q = 0.f;
    int nb = cpad >> 2;
    if (nb == 0) return q;
    const int4* L = (const int4*)lst;
    int4 id = L[0];
    float a0 = wsm[id.x * OO + o], a1 = wsm[id.y * OO + o],
          a2 = wsm[id.z * OO + o], a3 = wsm[id.w * OO + o];
    for (int b = 1; b < nb; b++) {
        int4 idn = L[b];
        float n0 = wsm[idn.x * OO + o], n1 = wsm[idn.y * OO + o],
              n2 = wsm[idn.z * OO + o], n3 = wsm[idn.w * OO + o];
        q = __fadd_rn(q, a0); q = __fadd_rn(q, a1);
        q = __fadd_rn(q, a2); q = __fadd_rn(q, a3);
        a0 = n0; a1 = n1; a2 = n2; a3 = n3;
    }
    q = __fadd_rn(q, a0); q = __fadd_rn(q, a1);
    q = __fadd_rn(q, a2); q = __fadd_rn(q, a3);
    return q;
}

__device__ __forceinline__ float decay(float tau)
{
    float u = __fdiv_rn(-1.0f, tau);
    return (float)exp((double)u);
}

// ---------------------------------------------------------------------------
// Kernel 2: the scan. 128 CTAs x 256 threads; group r = batch row.
// Named per-group barriers (bar 1 / bar 2, 128 threads each).
// Weight matrices have an appended zero row (index 128) for list padding.
// ---------------------------------------------------------------------------
#define WROW 129
#define SCAN_SMEM_BYTES ((WROW*128*3 + WROW*20)*4 + 512*4 + 64)

__global__ __launch_bounds__(256, 1) void scan_kernel(
    const float* __restrict__ xin,
    const float* __restrict__ mask,
    const float* __restrict__ w_h1h1, const float* __restrict__ b_h1h1,
    const float* __restrict__ w_h1h2, const float* __restrict__ b_h1h2,
    const float* __restrict__ w_h2h2, const float* __restrict__ b_h2h2,
    const float* __restrict__ w_h2o,  const float* __restrict__ b_h2o,
    const float* __restrict__ tau_adp_h1, const float* __restrict__ tau_adp_h2,
    const float* __restrict__ tau_m_h1,   const float* __restrict__ tau_m_h2,
    const float* __restrict__ tau_m_o,
    const float* __restrict__ hid1_mem0,  const float* __restrict__ hid2_mem0,
    const float* __restrict__ out_mem0,
    float* __restrict__ om_out,
    float* __restrict__ out)
{
    extern __shared__ unsigned char smraw[];
    float* w11s = (float*)smraw;                 // 129*128
    float* w12s = w11s + WROW * 128;             // 129*128
    float* w22s = w12s + WROW * 128;             // 129*128
    float* w2os = w22s + WROW * 128;             // 129*20
    int*   list1 = (int*)(w2os + WROW * 20);     // [2][128]
    int*   list2 = list1 + 256;                  // [2][128]
    unsigned* m1s = (unsigned*)(list2 + 256);    // [2][4]
    unsigned* m2s = m1s + 8;                     // [2][4]

    const int tid  = threadIdx.x;
    const int r    = tid >> 7;
    const int h    = tid & 127;
    const int wid  = tid >> 5;
    const int lane = tid & 31;
    const int seg  = wid & 3;
    const int grow = blockIdx.x * 2 + r;
    const int barid = 1 + r;

    // ---- load weights (masked) + zero pad rows ----
    for (int i = tid; i < 16384; i += 256) {
        w11s[i] = __fmul_rn(w_h1h1[i], mask[i]);
        w12s[i] = w_h1h2[i];
        w22s[i] = __fmul_rn(w_h2h2[i], mask[16384 + i]);
    }
    for (int i = tid; i < 2560; i += 256) w2os[i] = w_h2o[i];
    if (tid < 128) {
        w11s[16384 + tid] = 0.f;
        w12s[16384 + tid] = 0.f;
        w22s[16384 + tid] = 0.f;
    }
    if (tid < 20) w2os[2560 + tid] = 0.f;

    const float a1 = decay(tau_m_h1[h]);
    const float r1 = decay(tau_adp_h1[h]);
    const float a2 = decay(tau_m_h2[h]);
    const float r2 = decay(tau_adp_h2[h]);
    const float oma1 = __fsub_rn(1.0f, a1);
    const float omr1 = __fsub_rn(1.0f, r1);
    const float oma2 = __fsub_rn(1.0f, a2);
    const float omr2 = __fsub_rn(1.0f, r2);
    const float b11r = b_h1h1[h];
    const float b12a = b_h1h2[h];
    const float b12b = b_h2h2[h];

    float h1m = hid1_mem0[grow * HH + h];
    float h2m = hid2_mem0[grow * HH + h];
    float b1 = B_J0, b2 = B_J0;
    float h1sp = 0.f, h2sp = 0.f;
    float s1c = 0.f, s2c = 0.f;
    int c1p = 0, c2p = 0;   // padded counts

    const bool ro = (wid == 0) || (wid == 5);
    float om = 0.f, aoo = 0.f, omao = 0.f, bo = 0.f;
    if (ro && lane < OO) {
        om   = out_mem0[grow * OO + lane];
        aoo  = decay(tau_m_o[lane]);
        omao = __fsub_rn(1.0f, aoo);
        bo   = b_h2o[lane];
    }
    __syncthreads();

    float xt = xin[((size_t)0 * BT + grow) * HH + h];

    for (int t = 0; t < TT; t++) {
        float xnext = (t + 1 < TT) ? __ldg(&xin[((size_t)(t + 1) * BT + grow) * HH + h]) : 0.f;

        // ---- layer 1 ----
        float d11 = gather128(w11s, list1 + (r << 7), c1p, h);
        float i1 = __fadd_rn(__fadd_rn(xt, d11), b11r);
        b1 = __fadd_rn(__fmul_rn(r1, b1), __fmul_rn(omr1, h1sp));
        float B1 = __fadd_rn(B_J0, __fmul_rn(BETA, b1));
        h1m = __fsub_rn(__fadd_rn(__fmul_rn(h1m, a1), __fmul_rn(oma1, i1)),
                        __fmul_rn(B1, h1sp));
        float sp1 = (__fsub_rn(h1m, B1) > 0.0f) ? 1.0f : 0.0f;
        s1c += sp1;

        unsigned bal1 = __ballot_sync(0xffffffffu, sp1 != 0.0f);
        if (lane == 0) m1s[r * 4 + seg] = bal1;
        asm volatile("bar.sync %0, 128;" :: "r"(barid) : "memory");   // B1

        unsigned M0 = m1s[r * 4 + 0], M1 = m1s[r * 4 + 1];
        unsigned M2 = m1s[r * 4 + 2], M3 = m1s[r * 4 + 3];
        int c1n = __popc(M0) + __popc(M1) + __popc(M2) + __popc(M3);
        int c1np = (c1n + 3) & ~3;
        {
            int off = (seg > 0 ? __popc(M0) : 0) + (seg > 1 ? __popc(M1) : 0)
                    + (seg > 2 ? __popc(M2) : 0);
            if (sp1 != 0.0f)
                list1[(r << 7) + off + __popc(bal1 & ((1u << lane) - 1u))] = h;
            if (h >= c1n && h < c1np)
                list1[(r << 7) + h] = 128;
        }
        asm volatile("bar.sync %0, 128;" :: "r"(barid) : "memory");   // B2

        // ---- layer 2 ----
        float d12 = gather128(w12s, list1 + (r << 7), c1np, h);
        float d22 = gather128(w22s, list2 + (r << 7), c2p, h);
        float i2 = __fadd_rn(__fadd_rn(__fadd_rn(d12, b12a), d22), b12b);
        b2 = __fadd_rn(__fmul_rn(r2, b2), __fmul_rn(omr2, h2sp));
        float B2 = __fadd_rn(B_J0, __fmul_rn(BETA, b2));
        h2m = __fsub_rn(__fadd_rn(__fmul_rn(h2m, a2), __fmul_rn(oma2, i2)),
                        __fmul_rn(B2, h2sp));
        float sp2 = (__fsub_rn(h2m, B2) > 0.0f) ? 1.0f : 0.0f;
        s2c += sp2;

        unsigned bal2 = __ballot_sync(0xffffffffu, sp2 != 0.0f);
        if (lane == 0) m2s[r * 4 + seg] = bal2;
        asm volatile("bar.sync %0, 128;" :: "r"(barid) : "memory");   // B3

        unsigned N0 = m2s[r * 4 + 0], N1 = m2s[r * 4 + 1];
        unsigned N2 = m2s[r * 4 + 2], N3 = m2s[r * 4 + 3];
        int c2n = __popc(N0) + __popc(N1) + __popc(N2) + __popc(N3);
        int c2np = (c2n + 3) & ~3;
        {
            int off = (seg > 0 ? __popc(N0) : 0) + (seg > 1 ? __popc(N1) : 0)
                    + (seg > 2 ? __popc(N2) : 0);
            if (sp2 != 0.0f)
                list2[(r << 7) + off + __popc(bal2 & ((1u << lane) - 1u))] = h;
            if (h >= c2n && h < c2np)
                list2[(r << 7) + h] = 128;
        }
        asm volatile("bar.sync %0, 128;" :: "r"(barid) : "memory");   // B4

        // ---- readout: om update only; softmax deferred to post-kernel ----
        if (ro) {
            int oo = (lane < OO) ? lane : 0;
            float d2o = gather20(w2os, list2 + (r << 7), c2np, oo);
            float io = __fadd_rn(d2o, bo);
            om = __fadd_rn(__fmul_rn(om, aoo), __fmul_rn(omao, io));
            if (lane < OO)
                om_out[((size_t)t * BT + grow) * OO + lane] = om;
        }

        h1sp = sp1;
        h2sp = sp2;
        c1p = c1np;
        c2p = c2np;
        xt = xnext;
    }

    out[OUT_OFF_S1 + grow * HH + h] = __fdiv_rn(s1c, (float)TT);
    out[OUT_OFF_S2 + grow * HH + h] = __fdiv_rn(s2c, (float)TT);
}

// ---------------------------------------------------------------------------
// Kernel 2b: softmax + ascending-t accumulation per batch row.
// Same op order as reference: acc += softmax(om_t) for t = 11..249.
// ---------------------------------------------------------------------------
__global__ __launch_bounds__(256) void softmax_acc_kernel(
    const float* __restrict__ om_in, float* __restrict__ out)
{
    __shared__ float sm[(TT - 11) * OO];   // 239*20 = 4780 floats
    const int b = blockIdx.x;
    const int wid = threadIdx.x >> 5;
    const int lane = threadIdx.x & 31;

    for (int t = 11 + wid; t < TT; t += 8) {
        float om = (lane < OO) ? om_in[((size_t)t * BT + b) * OO + lane] : 0.f;
        float v = (lane < OO) ? om : -3.4e38f;
#pragma unroll
        for (int d = 16; d; d >>= 1) v = fmaxf(v, __shfl_xor_sync(0xffffffffu, v, d));
        float e = (lane < OO) ? expf(__fsub_rn(om, v)) : 0.f;
        float ssum = e;
#pragma unroll
        for (int d = 16; d; d >>= 1) ssum += __shfl_xor_sync(0xffffffffu, ssum, d);
        if (lane < OO) sm[(t - 11) * OO + lane] = __fdiv_rn(e, ssum);
    }
    __syncthreads();

    if (threadIdx.x < OO) {
        float a = 0.f;
        for (int tt = 0; tt < TT - 11; tt++)
            a = __fadd_rn(a, sm[tt * OO + threadIdx.x]);
        out[OUT_OFF_ACC + b * OO + threadIdx.x] = a;
    }
}

// ---------------------------------------------------------------------------
// Kernel 3a/3b: A_norm (deterministic two-pass)
// ---------------------------------------------------------------------------
__global__ __launch_bounds__(256) void norm_part_kernel(
    const float* __restrict__ w11, const float* __restrict__ w22,
    const float* __restrict__ mask)
{
    __shared__ float red[256];
    int i = blockIdx.x * 256 + threadIdx.x;
    float s = fabsf(__fmul_rn(w11[i], mask[i]))
            + fabsf(__fmul_rn(w22[i], mask[16384 + i]));
    red[threadIdx.x] = s;
    __syncthreads();
    for (int d = 128; d > 0; d >>= 1) {
        if (threadIdx.x < d) red[threadIdx.x] += red[threadIdx.x + d];
        __syncthreads();
    }
    if (threadIdx.x == 0) g_npart[blockIdx.x] = red[0];
}

__global__ void norm_finish_kernel(float* __restrict__ out)
{
    int lane = threadIdx.x;
    __shared__ float w[2];
    float s = g_npart[lane];
#pragma unroll
    for (int d = 16; d; d >>= 1) s += __shfl_xor_sync(0xffffffffu, s, d);
    if ((lane & 31) == 0) w[lane >> 5] = s;
    __syncthreads();
    if (lane == 0) out[OUT_OFF_NORM] = w[0] + w[1];
}

// ---------------------------------------------------------------------------
extern "C" void kernel_launch(void* const* d_in, const int* in_sizes, int n_in,
                              void* d_out, int out_size)
{
    const float* x          = (const float*)d_in[0];
    const float* mask       = (const float*)d_in[1];
    const float* w_ih1      = (const float*)d_in[2];
    const float* b_ih1      = (const float*)d_in[3];
    const float* w_h1h1     = (const float*)d_in[4];
    const float* b_h1h1     = (const float*)d_in[5];
    const float* w_h1h2     = (const float*)d_in[6];
    const float* b_h1h2     = (const float*)d_in[7];
    const float* w_h2h2     = (const float*)d_in[8];
    const float* b_h2h2     = (const float*)d_in[9];
    const float* w_h2o      = (const float*)d_in[10];
    const float* b_h2o      = (const float*)d_in[11];
    const float* tau_adp_h1 = (const float*)d_in[12];
    const float* tau_adp_h2 = (const float*)d_in[13];
    const float* tau_m_h1   = (const float*)d_in[14];
    const float* tau_m_h2   = (const float*)d_in[15];
    const float* tau_m_o    = (const float*)d_in[16];
    const float* hid1_mem0  = (const float*)d_in[17];
    const float* hid2_mem0  = (const float*)d_in[18];
    const float* out_mem0   = (const float*)d_in[19];
    float* out = (float*)d_out;

    float* xin = nullptr;
    cudaGetSymbolAddress((void**)&xin, g_xin);
    float* omb = nullptr;
    cudaGetSymbolAddress((void**)&omb, g_om);

    cudaFuncSetAttribute(scan_kernel, cudaFuncAttributeMaxDynamicSharedMemorySize,
                         SCAN_SMEM_BYTES);

    gemm_xin_kernel<<<(BT * TT) / GTM, 256>>>(x, w_ih1, b_ih1, xin);
    scan_kernel<<<BT / 2, 256, SCAN_SMEM_BYTES>>>(
        xin, mask, w_h1h1, b_h1h1, w_h1h2, b_h1h2, w_h2h2, b_h2h2,
        w_h2o, b_h2o, tau_adp_h1, tau_adp_h2, tau_m_h1, tau_m_h2, tau_m_o,
        hid1_mem0, hid2_mem0, out_mem0, omb, out);
    softmax_acc_kernel<<<BT, 256>>>(omb, out);
    norm_part_kernel<<<64, 256>>>(w_h1h1, w_h2h2, mask);
    norm_finish_kernel<<<1, 64>>>(out);
}

// round 9
// speedup vs baseline: 1.6895x; 1.1576x over previous
#include <cuda_runtime.h>
#include <cuda_bf16.h>
#include <math.h>

// Problem constants
#define BT   256
#define TT   250
#define II   700
#define HH   128
#define OO   20
#define B_J0 0.01f
#define BETA 1.8f

// Output layout: output[256*20], s1[256*128], s2[256*128], A_norm[1]
#define OUT_OFF_ACC  0
#define OUT_OFF_S1   (BT*OO)
#define OUT_OFF_S2   (OUT_OFF_S1 + BT*HH)
#define OUT_OFF_NORM (OUT_OFF_S2 + BT*HH)

// Static device scratch (no allocations allowed)
__device__ float g_xin[TT * BT * HH];   // 32 MB
__device__ float g_om[TT * BT * OO];    // 5.12 MB
__device__ float g_npart[64];

// ---------------------------------------------------------------------------
// f32x2 helpers
// ---------------------------------------------------------------------------
__device__ __forceinline__ unsigned long long ffma2(unsigned long long a,
                                                    unsigned long long b,
                                                    unsigned long long c)
{
    unsigned long long d;
    asm("fma.rn.f32x2 %0, %1, %2, %3;" : "=l"(d) : "l"(a), "l"(b), "l"(c));
    return d;
}
__device__ __forceinline__ unsigned long long pack2(float lo, float hi)
{
    unsigned long long d;
    asm("mov.b64 %0, {%1, %2};" : "=l"(d) : "f"(lo), "f"(hi));
    return d;
}
__device__ __forceinline__ float2 unpack2(unsigned long long v)
{
    float lo, hi;
    asm("mov.b64 {%0, %1}, %2;" : "=f"(lo), "=f"(hi) : "l"(v));
    return make_float2(lo, hi);
}

// ---------------------------------------------------------------------------
// Kernel 1: xin = einsum('bti,ih->tbh', x, w_ih1) + b_ih1
// 128x128 CTA tile (500 CTAs, 2 CTAs/SM), 8Mx8N per thread via FFMA2 M-pairs.
// Single accumulator per element, strictly ascending k -> bit-exact.
// ---------------------------------------------------------------------------
#define GTM 128
#define KT  8
#define NKTILE ((II + KT - 1) / KT)   // 88

__global__ __launch_bounds__(256, 2) void gemm_xin_kernel(
    const float* __restrict__ x,
    const float* __restrict__ w,
    const float* __restrict__ bias,
    float* __restrict__ xin)
{
    __shared__ float As[2][KT][GTM];  // 8 KB
    __shared__ float Bs[2][KT][HH];   // 8 KB

    const int tid = threadIdx.x;
    const int tx = tid & 15;
    const int ty = tid >> 4;          // 0..15
    const int bm = blockIdx.x * GTM;
    const int n0 = tx * 8;
    const int m0 = ty * 8;            // 8 rows = 4 pairs

    unsigned long long acc[4][8];
#pragma unroll
    for (int p = 0; p < 4; p++)
#pragma unroll
        for (int j = 0; j < 8; j++) acc[p][j] = 0ull;

    // A loader: row = tid&127, k quad = (tid>>7)*4
    const int la_m = tid & 127;
    const int la_k = (tid >> 7) * 4;
    const float* xrow = x + (size_t)(bm + la_m) * II + la_k;
    // B loader
    const int bk = tid >> 5;          // 0..7
    const int bn = (tid & 31) * 4;

    {
        float4 av = *(const float4*)(xrow);
        float4 bv = *(const float4*)(w + (size_t)bk * HH + bn);
        As[0][la_k + 0][la_m] = av.x;
        As[0][la_k + 1][la_m] = av.y;
        As[0][la_k + 2][la_m] = av.z;
        As[0][la_k + 3][la_m] = av.w;
        *(float4*)&Bs[0][bk][bn] = bv;
    }
    __syncthreads();

    for (int tI = 0; tI < NKTILE; tI++) {
        const int buf = tI & 1;
        float4 nav, nbv;
        const bool has = (tI + 1 < NKTILE);
        if (has) {
            int k0 = (tI + 1) * KT;
            nav = (k0 + la_k + 3 < II) ? *(const float4*)(xrow + k0)
                                       : make_float4(0.f, 0.f, 0.f, 0.f);
            int kk = k0 + bk;
            nbv = (kk < II) ? *(const float4*)(w + (size_t)kk * HH + bn)
                            : make_float4(0.f, 0.f, 0.f, 0.f);
        }

#pragma unroll
        for (int k = 0; k < KT; k++) {
            unsigned long long a[4];
            const ulonglong2* Ap = (const ulonglong2*)&As[buf][k][m0];
            ulonglong2 av;
            av = Ap[0]; a[0] = av.x; a[1] = av.y;
            av = Ap[1]; a[2] = av.x; a[3] = av.y;
            float4 b0 = *(const float4*)&Bs[buf][k][n0];
            float4 b1 = *(const float4*)&Bs[buf][k][n0 + 4];
            float bj[8] = {b0.x, b0.y, b0.z, b0.w, b1.x, b1.y, b1.z, b1.w};
#pragma unroll
            for (int j = 0; j < 8; j++) {
                unsigned long long bb = pack2(bj[j], bj[j]);
#pragma unroll
                for (int p = 0; p < 4; p++)
                    acc[p][j] = ffma2(a[p], bb, acc[p][j]);
            }
        }

        if (has) {
            int nb = buf ^ 1;
            As[nb][la_k + 0][la_m] = nav.x;
            As[nb][la_k + 1][la_m] = nav.y;
            As[nb][la_k + 2][la_m] = nav.z;
            As[nb][la_k + 3][la_m] = nav.w;
            *(float4*)&Bs[nb][bk][bn] = nbv;
        }
        __syncthreads();
    }

    float bn8[8];
#pragma unroll
    for (int j = 0; j < 8; j++) bn8[j] = bias[n0 + j];

#pragma unroll
    for (int p = 0; p < 4; p++) {
        float lo[8], hi[8];
#pragma unroll
        for (int j = 0; j < 8; j++) {
            float2 v = unpack2(acc[p][j]);
            lo[j] = v.x; hi[j] = v.y;
        }
        int mg = bm + m0 + 2 * p;
#pragma unroll
        for (int half = 0; half < 2; half++) {
            const float* vv = half ? hi : lo;
            int m = mg + half;
            int bb = m / TT;
            int tt = m - bb * TT;
            float* op = xin + ((size_t)tt * BT + bb) * HH + n0;
            float4 v0, v1;
            v0.x = __fadd_rn(vv[0], bn8[0]);
            v0.y = __fadd_rn(vv[1], bn8[1]);
            v0.z = __fadd_rn(vv[2], bn8[2]);
            v0.w = __fadd_rn(vv[3], bn8[3]);
            v1.x = __fadd_rn(vv[4], bn8[4]);
            v1.y = __fadd_rn(vv[5], bn8[5]);
            v1.z = __fadd_rn(vv[6], bn8[6]);
            v1.w = __fadd_rn(vv[7], bn8[7]);
            *(float4*)(op)     = v0;
            *(float4*)(op + 4) = v1;
        }
    }
}

// ---------------------------------------------------------------------------
// Fused DUAL gather over one padded ascending list: two independent add
// chains (ILP-2) in one loop. Each chain: single accumulator, ascending
// order, pure __fadd_rn -> bit-identical per dot product. Pad index 128
// hits appended zero rows (q + 0.0f exact).
// SB = row stride of matrix B (128 or 20).
// ---------------------------------------------------------------------------
template<int SB>
__device__ __forceinline__ void dual_gather(const float* __restrict__ wa,
                                            const float* __restrict__ wb,
                                            const int* __restrict__ lst,
                                            int cpad, int ca, int cb,
                                            float& qa, float& qb)
{
    float A = 0.f, B = 0.f;
    int nb = cpad >> 2;
    if (nb) {
        const int4* L = (const int4*)lst;
        int4 id = L[0];
        float a0 = wa[(id.x << 7) + ca], a1 = wa[(id.y << 7) + ca];
        float a2 = wa[(id.z << 7) + ca], a3 = wa[(id.w << 7) + ca];
        float b0 = wb[id.x * SB + cb],   b1 = wb[id.y * SB + cb];
        float b2 = wb[id.z * SB + cb],   b3 = wb[id.w * SB + cb];
        for (int b = 1; b < nb; b++) {
            int4 idn = L[b];
            float na0 = wa[(idn.x << 7) + ca], na1 = wa[(idn.y << 7) + ca];
            float na2 = wa[(idn.z << 7) + ca], na3 = wa[(idn.w << 7) + ca];
            float nb0 = wb[idn.x * SB + cb],   nb1 = wb[idn.y * SB + cb];
            float nb2 = wb[idn.z * SB + cb],   nb3 = wb[idn.w * SB + cb];
            A = __fadd_rn(A, a0); B = __fadd_rn(B, b0);
            A = __fadd_rn(A, a1); B = __fadd_rn(B, b1);
            A = __fadd_rn(A, a2); B = __fadd_rn(B, b2);
            A = __fadd_rn(A, a3); B = __fadd_rn(B, b3);
            a0 = na0; a1 = na1; a2 = na2; a3 = na3;
            b0 = nb0; b1 = nb1; b2 = nb2; b3 = nb3;
        }
        A = __fadd_rn(A, a0); B = __fadd_rn(B, b0);
        A = __fadd_rn(A, a1); B = __fadd_rn(B, b1);
        A = __fadd_rn(A, a2); B = __fadd_rn(B, b2);
        A = __fadd_rn(A, a3); B = __fadd_rn(B, b3);
    }
    qa = A; qb = B;
}

__device__ __forceinline__ float decay(float tau)
{
    float u = __fdiv_rn(-1.0f, tau);
    return (float)exp((double)u);
}

// ---------------------------------------------------------------------------
// Kernel 2: the scan. 128 CTAs x 256 threads; group r = batch row.
// Per-step structure (cross-step gather hoisting):
//   L1 update (uses d11 from prev step's dual) -> list1
//   dual(w12, w11) over list1 -> d12(t), d11(t+1)
//   L2 update -> list2
//   dual(w22, w2o) over list2 -> d22(t+1), d2o(t)
//   om update (softmax deferred)
// ---------------------------------------------------------------------------
#define WROW 129
#define SCAN_SMEM_BYTES ((WROW*128*3 + WROW*20)*4 + 512*4 + 64)

__global__ __launch_bounds__(256, 1) void scan_kernel(
    const float* __restrict__ xin,
    const float* __restrict__ mask,
    const float* __restrict__ w_h1h1, const float* __restrict__ b_h1h1,
    const float* __restrict__ w_h1h2, const float* __restrict__ b_h1h2,
    const float* __restrict__ w_h2h2, const float* __restrict__ b_h2h2,
    const float* __restrict__ w_h2o,  const float* __restrict__ b_h2o,
    const float* __restrict__ tau_adp_h1, const float* __restrict__ tau_adp_h2,
    const float* __restrict__ tau_m_h1,   const float* __restrict__ tau_m_h2,
    const float* __restrict__ tau_m_o,
    const float* __restrict__ hid1_mem0,  const float* __restrict__ hid2_mem0,
    const float* __restrict__ out_mem0,
    float* __restrict__ om_out,
    float* __restrict__ out)
{
    extern __shared__ unsigned char smraw[];
    float* w11s = (float*)smraw;                 // 129*128
    float* w12s = w11s + WROW * 128;             // 129*128
    float* w22s = w12s + WROW * 128;             // 129*128
    float* w2os = w22s + WROW * 128;             // 129*20
    int*   list1 = (int*)(w2os + WROW * 20);     // [2][128]
    int*   list2 = list1 + 256;                  // [2][128]
    unsigned* m1s = (unsigned*)(list2 + 256);    // [2][4]
    unsigned* m2s = m1s + 8;                     // [2][4]

    const int tid  = threadIdx.x;
    const int r    = tid >> 7;
    const int h    = tid & 127;
    const int wid  = tid >> 5;
    const int lane = tid & 31;
    const int seg  = wid & 3;
    const int grow = blockIdx.x * 2 + r;
    const int barid = 1 + r;

    for (int i = tid; i < 16384; i += 256) {
        w11s[i] = __fmul_rn(w_h1h1[i], mask[i]);
        w12s[i] = w_h1h2[i];
        w22s[i] = __fmul_rn(w_h2h2[i], mask[16384 + i]);
    }
    for (int i = tid; i < 2560; i += 256) w2os[i] = w_h2o[i];
    if (tid < 128) {
        w11s[16384 + tid] = 0.f;
        w12s[16384 + tid] = 0.f;
        w22s[16384 + tid] = 0.f;
    }
    if (tid < 20) w2os[2560 + tid] = 0.f;

    const float a1 = decay(tau_m_h1[h]);
    const float r1 = decay(tau_adp_h1[h]);
    const float a2 = decay(tau_m_h2[h]);
    const float r2 = decay(tau_adp_h2[h]);
    const float oma1 = __fsub_rn(1.0f, a1);
    const float omr1 = __fsub_rn(1.0f, r1);
    const float oma2 = __fsub_rn(1.0f, a2);
    const float omr2 = __fsub_rn(1.0f, r2);
    const float b11r = b_h1h1[h];
    const float b12a = b_h1h2[h];
    const float b12b = b_h2h2[h];

    float h1m = hid1_mem0[grow * HH + h];
    float h2m = hid2_mem0[grow * HH + h];
    float b1 = B_J0, b2 = B_J0;
    float h1sp = 0.f, h2sp = 0.f;
    float s1c = 0.f, s2c = 0.f;
    float d11 = 0.f, d22 = 0.f;   // hoisted gathers for current step

    const bool ro = (wid == 0) || (wid == 5);
    const int oo = (lane < OO) ? lane : 0;
    float om = 0.f, aoo = 0.f, omao = 0.f, bo = 0.f;
    if (ro && lane < OO) {
        om   = out_mem0[grow * OO + lane];
        aoo  = decay(tau_m_o[lane]);
        omao = __fsub_rn(1.0f, aoo);
        bo   = b_h2o[lane];
    }
    __syncthreads();

    float xt = xin[((size_t)0 * BT + grow) * HH + h];

    for (int t = 0; t < TT; t++) {
        float xnext = (t + 1 < TT) ? __ldg(&xin[((size_t)(t + 1) * BT + grow) * HH + h]) : 0.f;

        // ---- layer 1 (d11 precomputed last step) ----
        float i1 = __fadd_rn(__fadd_rn(xt, d11), b11r);
        b1 = __fadd_rn(__fmul_rn(r1, b1), __fmul_rn(omr1, h1sp));
        float B1 = __fadd_rn(B_J0, __fmul_rn(BETA, b1));
        h1m = __fsub_rn(__fadd_rn(__fmul_rn(h1m, a1), __fmul_rn(oma1, i1)),
                        __fmul_rn(B1, h1sp));
        float sp1 = (__fsub_rn(h1m, B1) > 0.0f) ? 1.0f : 0.0f;
        s1c += sp1;

        unsigned bal1 = __ballot_sync(0xffffffffu, sp1 != 0.0f);
        if (lane == 0) m1s[r * 4 + seg] = bal1;
        asm volatile("bar.sync %0, 128;" :: "r"(barid) : "memory");   // B1

        unsigned M0 = m1s[r * 4 + 0], M1 = m1s[r * 4 + 1];
        unsigned M2 = m1s[r * 4 + 2], M3 = m1s[r * 4 + 3];
        int c1n = __popc(M0) + __popc(M1) + __popc(M2) + __popc(M3);
        int c1np = (c1n + 3) & ~3;
        {
            int off = (seg > 0 ? __popc(M0) : 0) + (seg > 1 ? __popc(M1) : 0)
                    + (seg > 2 ? __popc(M2) : 0);
            if (sp1 != 0.0f)
                list1[(r << 7) + off + __popc(bal1 & ((1u << lane) - 1u))] = h;
            if (h >= c1n && h < c1np)
                list1[(r << 7) + h] = 128;
        }
        asm volatile("bar.sync %0, 128;" :: "r"(barid) : "memory");   // B2

        // ---- dual gather: d12(t) and d11(t+1), both over list1 ----
        float d12, d11n;
        dual_gather<128>(w12s, w11s, list1 + (r << 7), c1np, h, h, d12, d11n);

        // ---- layer 2 (d22 precomputed last step) ----
        float i2 = __fadd_rn(__fadd_rn(__fadd_rn(d12, b12a), d22), b12b);
        b2 = __fadd_rn(__fmul_rn(r2, b2), __fmul_rn(omr2, h2sp));
        float B2 = __fadd_rn(B_J0, __fmul_rn(BETA, b2));
        h2m = __fsub_rn(__fadd_rn(__fmul_rn(h2m, a2), __fmul_rn(oma2, i2)),
                        __fmul_rn(B2, h2sp));
        float sp2 = (__fsub_rn(h2m, B2) > 0.0f) ? 1.0f : 0.0f;
        s2c += sp2;

        unsigned bal2 = __ballot_sync(0xffffffffu, sp2 != 0.0f);
        if (lane == 0) m2s[r * 4 + seg] = bal2;
        asm volatile("bar.sync %0, 128;" :: "r"(barid) : "memory");   // B3

        unsigned N0 = m2s[r * 4 + 0], N1 = m2s[r * 4 + 1];
        unsigned N2 = m2s[r * 4 + 2], N3 = m2s[r * 4 + 3];
        int c2n = __popc(N0) + __popc(N1) + __popc(N2) + __popc(N3);
        int c2np = (c2n + 3) & ~3;
        {
            int off = (seg > 0 ? __popc(N0) : 0) + (seg > 1 ? __popc(N1) : 0)
                    + (seg > 2 ? __popc(N2) : 0);
            if (sp2 != 0.0f)
                list2[(r << 7) + off + __popc(bal2 & ((1u << lane) - 1u))] = h;
            if (h >= c2n && h < c2np)
                list2[(r << 7) + h] = 128;
        }
        asm volatile("bar.sync %0, 128;" :: "r"(barid) : "memory");   // B4

        // ---- dual gather: d22(t+1) and d2o(t) (all threads, lockstep) ----
        float d22n, d2o;
        dual_gather<20>(w22s, w2os, list2 + (r << 7), c2np, h, oo, d22n, d2o);

        // ---- readout om update (softmax deferred to post-kernel) ----
        if (ro) {
            float io = __fadd_rn(d2o, bo);
            om = __fadd_rn(__fmul_rn(om, aoo), __fmul_rn(omao, io));
            if (lane < OO)
                om_out[((size_t)t * BT + grow) * OO + lane] = om;
        }

        h1sp = sp1;
        h2sp = sp2;
        d11 = d11n;
        d22 = d22n;
        xt = xnext;
    }

    out[OUT_OFF_S1 + grow * HH + h] = __fdiv_rn(s1c, (float)TT);
    out[OUT_OFF_S2 + grow * HH + h] = __fdiv_rn(s2c, (float)TT);
}

// ---------------------------------------------------------------------------
// Kernel 2b: softmax + ascending-t accumulation per batch row.
// ---------------------------------------------------------------------------
__global__ __launch_bounds__(256) void softmax_acc_kernel(
    const float* __restrict__ om_in, float* __restrict__ out)
{
    __shared__ float sm[(TT - 11) * OO];
    const int b = blockIdx.x;
    const int wid = threadIdx.x >> 5;
    const int lane = threadIdx.x & 31;

    for (int t = 11 + wid; t < TT; t += 8) {
        float om = (lane < OO) ? om_in[((size_t)t * BT + b) * OO + lane] : 0.f;
        float v = (lane < OO) ? om : -3.4e38f;
#pragma unroll
        for (int d = 16; d; d >>= 1) v = fmaxf(v, __shfl_xor_sync(0xffffffffu, v, d));
        float e = (lane < OO) ? expf(__fsub_rn(om, v)) : 0.f;
        float ssum = e;
#pragma unroll
        for (int d = 16; d; d >>= 1) ssum += __shfl_xor_sync(0xffffffffu, ssum, d);
        if (lane < OO) sm[(t - 11) * OO + lane] = __fdiv_rn(e, ssum);
    }
    __syncthreads();

    if (threadIdx.x < OO) {
        float a = 0.f;
        for (int tt = 0; tt < TT - 11; tt++)
            a = __fadd_rn(a, sm[tt * OO + threadIdx.x]);
        out[OUT_OFF_ACC + b * OO + threadIdx.x] = a;
    }
}

// ---------------------------------------------------------------------------
// Kernel 3a/3b: A_norm (deterministic two-pass)
// ---------------------------------------------------------------------------
__global__ __launch_bounds__(256) void norm_part_kernel(
    const float* __restrict__ w11, const float* __restrict__ w22,
    const float* __restrict__ mask)
{
    __shared__ float red[256];
    int i = blockIdx.x * 256 + threadIdx.x;
    float s = fabsf(__fmul_rn(w11[i], mask[i]))
            + fabsf(__fmul_rn(w22[i], mask[16384 + i]));
    red[threadIdx.x] = s;
    __syncthreads();
    for (int d = 128; d > 0; d >>= 1) {
        if (threadIdx.x < d) red[threadIdx.x] += red[threadIdx.x + d];
        __syncthreads();
    }
    if (threadIdx.x == 0) g_npart[blockIdx.x] = red[0];
}

__global__ void norm_finish_kernel(float* __restrict__ out)
{
    int lane = threadIdx.x;
    __shared__ float w[2];
    float s = g_npart[lane];
#pragma unroll
    for (int d = 16; d; d >>= 1) s += __shfl_xor_sync(0xffffffffu, s, d);
    if ((lane & 31) == 0) w[lane >> 5] = s;
    __syncthreads();
    if (lane == 0) out[OUT_OFF_NORM] = w[0] + w[1];
}

// ---------------------------------------------------------------------------
extern "C" void kernel_launch(void* const* d_in, const int* in_sizes, int n_in,
                              void* d_out, int out_size)
{
    const float* x          = (const float*)d_in[0];
    const float* mask       = (const float*)d_in[1];
    const float* w_ih1      = (const float*)d_in[2];
    const float* b_ih1      = (const float*)d_in[3];
    const float* w_h1h1     = (const float*)d_in[4];
    const float* b_h1h1     = (const float*)d_in[5];
    const float* w_h1h2     = (const float*)d_in[6];
    const float* b_h1h2     = (const float*)d_in[7];
    const float* w_h2h2     = (const float*)d_in[8];
    const float* b_h2h2     = (const float*)d_in[9];
    const float* w_h2o      = (const float*)d_in[10];
    const float* b_h2o      = (const float*)d_in[11];
    const float* tau_adp_h1 = (const float*)d_in[12];
    const float* tau_adp_h2 = (const float*)d_in[13];
    const float* tau_m_h1   = (const float*)d_in[14];
    const float* tau_m_h2   = (const float*)d_in[15];
    const float* tau_m_o    = (const float*)d_in[16];
    const float* hid1_mem0  = (const float*)d_in[17];
    const float* hid2_mem0  = (const float*)d_in[18];
    const float* out_mem0   = (const float*)d_in[19];
    float* out = (float*)d_out;

    float* xin = nullptr;
    cudaGetSymbolAddress((void**)&xin, g_xin);
    float* omb = nullptr;
    cudaGetSymbolAddress((void**)&omb, g_om);

    cudaFuncSetAttribute(scan_kernel, cudaFuncAttributeMaxDynamicSharedMemorySize,
                         SCAN_SMEM_BYTES);

    gemm_xin_kernel<<<(BT * TT) / GTM, 256>>>(x, w_ih1, b_ih1, xin);
    scan_kernel<<<BT / 2, 256, SCAN_SMEM_BYTES>>>(
        xin, mask, w_h1h1, b_h1h1, w_h1h2, b_h1h2, w_h2h2, b_h2h2,
        w_h2o, b_h2o, tau_adp_h1, tau_adp_h2, tau_m_h1, tau_m_h2, tau_m_o,
        hid1_mem0, hid2_mem0, out_mem0, omb, out);
    softmax_acc_kernel<<<BT, 256>>>(omb, out);
    norm_part_kernel<<<64, 256>>>(w_h1h1, w_h2h2, mask);
    norm_finish_kernel<<<1, 64>>>(out);
}